// round 14
// baseline (speedup 1.0000x reference)
#include <cuda_runtime.h>
#include <cuda_bf16.h>

#define NB    4096
#define GDIM  2016
#define S     68
#define MS    (64 * S)          // 4352 floats
#define SB2   72                // bf16 row stride
#define BMB   9216              // bytes per bf16 matrix

// k_main smem: 6 bf16 matrices + 16 reduction floats
#define KM_SMEM_BYTES (6 * BMB + 64)
// k_ec smem: 4 f32 matrices + 256 vec + pad
#define KE_SMEM_BYTES ((4 * MS + 256 + 16) * sizeof(float))

__device__ float g_gi[NB * GDIM];
__device__ float g_z9[NB * 4096];

__device__ __forceinline__ unsigned f2tf32_rna(float f) {
    unsigned u;
    asm("cvt.rna.tf32.f32 %0, %1;" : "=r"(u) : "f"(f));
    return u;
}
__device__ __forceinline__ unsigned pack_bf16x2(float lo, float hi) {
    unsigned u;
    asm("cvt.rn.bf16x2.f32 %0, %1, %2;" : "=r"(u) : "f"(hi), "f"(lo));
    return u;
}
__device__ __forceinline__ unsigned smem_u32(const void* p) {
    return (unsigned)__cvta_generic_to_shared(p);
}
__device__ __forceinline__ void ldm_x4(unsigned* r, unsigned addr) {
    asm volatile("ldmatrix.sync.aligned.m8n8.x4.shared.b16 {%0,%1,%2,%3}, [%4];"
                 : "=r"(r[0]), "=r"(r[1]), "=r"(r[2]), "=r"(r[3]) : "r"(addr));
}
__device__ __forceinline__ void ldm_x4_t(unsigned* r, unsigned addr) {
    asm volatile("ldmatrix.sync.aligned.m8n8.x4.trans.shared.b16 {%0,%1,%2,%3}, [%4];"
                 : "=r"(r[0]), "=r"(r[1]), "=r"(r[2]), "=r"(r[3]) : "r"(addr));
}
__device__ __forceinline__ void mma_tf32(float* c, unsigned a0, unsigned a1,
                                         unsigned a2, unsigned a3,
                                         unsigned b0, unsigned b1) {
    asm volatile(
        "mma.sync.aligned.m16n8k8.row.col.f32.tf32.tf32.f32 "
        "{%0,%1,%2,%3}, {%4,%5,%6,%7}, {%8,%9}, {%0,%1,%2,%3};"
        : "+f"(c[0]), "+f"(c[1]), "+f"(c[2]), "+f"(c[3])
        : "r"(a0), "r"(a1), "r"(a2), "r"(a3), "r"(b0), "r"(b1));
}
__device__ __forceinline__ void mma_bf16(float* c, unsigned a0, unsigned a1,
                                         unsigned a2, unsigned a3,
                                         unsigned b0, unsigned b1) {
    asm volatile(
        "mma.sync.aligned.m16n8k16.row.col.f32.bf16.bf16.f32 "
        "{%0,%1,%2,%3}, {%4,%5,%6,%7}, {%8,%9}, {%0,%1,%2,%3};"
        : "+f"(c[0]), "+f"(c[1]), "+f"(c[2]), "+f"(c[3])
        : "r"(a0), "r"(a1), "r"(a2), "r"(a3), "r"(b0), "r"(b1));
}

// EC-tf32 core: acc += X@Y at fp32 quality. X,Y f32 stride-S smem.
__device__ __forceinline__ void ec_accum(const float* X, const float* Y,
                                         float (*acc)[4][4],
                                         int wm, int wn, int gid, int tig) {
#pragma unroll
    for (int ks = 0; ks < 8; ks++) {
        const int k0 = ks * 8;
        float a_f[2][4], b_f[4][2];
#pragma unroll
        for (int mt = 0; mt < 2; mt++) {
            const float* ap = X + (wm + 16 * mt + gid) * S + k0 + tig;
            a_f[mt][0] = ap[0]; a_f[mt][1] = ap[8 * S];
            a_f[mt][2] = ap[4]; a_f[mt][3] = ap[8 * S + 4];
        }
#pragma unroll
        for (int nt = 0; nt < 4; nt++) {
            const float* bp = Y + (k0 + tig) * S + wn + 8 * nt + gid;
            b_f[nt][0] = bp[0]; b_f[nt][1] = bp[4 * S];
        }
        unsigned ahi[2][4], alo[2][4], bhi[4][2], blo[4][2];
#pragma unroll
        for (int mt = 0; mt < 2; mt++)
#pragma unroll
            for (int q = 0; q < 4; q++) {
                float x = a_f[mt][q]; unsigned h = f2tf32_rna(x);
                ahi[mt][q] = h; alo[mt][q] = __float_as_uint(x - __uint_as_float(h));
            }
#pragma unroll
        for (int nt = 0; nt < 4; nt++)
#pragma unroll
            for (int q = 0; q < 2; q++) {
                float x = b_f[nt][q]; unsigned h = f2tf32_rna(x);
                bhi[nt][q] = h; blo[nt][q] = __float_as_uint(x - __uint_as_float(h));
            }
#pragma unroll
        for (int mt = 0; mt < 2; mt++)
#pragma unroll
            for (int nt = 0; nt < 4; nt++) {
                mma_tf32(acc[mt][nt], ahi[mt][0], ahi[mt][1], ahi[mt][2], ahi[mt][3],
                         blo[nt][0], blo[nt][1]);
                mma_tf32(acc[mt][nt], alo[mt][0], alo[mt][1], alo[mt][2], alo[mt][3],
                         bhi[nt][0], bhi[nt][1]);
                mma_tf32(acc[mt][nt], ahi[mt][0], ahi[mt][1], ahi[mt][2], ahi[mt][3],
                         bhi[nt][0], bhi[nt][1]);
            }
    }
}

template<bool HAS_X, bool KEEP, bool PRESYNC>
__device__ __forceinline__ void mm_ec_step(const float* X, const float* Y,
                                           float* OUT, float a, float s,
                                           const float (*xres)[4][4],
                                           float (*ores)[4][4]) {
    const int t = threadIdx.x, lane = t & 31, w = t >> 5;
    const int gid = lane >> 2, tig = lane & 3;
    const int wm = (w >> 1) * 32, wn = (w & 1) * 32;

    float acc[2][4][4];
#pragma unroll
    for (int mt = 0; mt < 2; mt++)
#pragma unroll
        for (int nt = 0; nt < 4; nt++)
#pragma unroll
            for (int q = 0; q < 4; q++) acc[mt][nt][q] = 0.f;
    ec_accum(X, Y, acc, wm, wn, gid, tig);

    float res[2][4][4];
#pragma unroll
    for (int mt = 0; mt < 2; mt++)
#pragma unroll
        for (int nt = 0; nt < 4; nt++)
#pragma unroll
            for (int q = 0; q < 4; q++) {
                float v = s * acc[mt][nt][q];
                if (HAS_X) v += a * xres[mt][nt][q];
                res[mt][nt][q] = v;
            }
    if (PRESYNC) __syncthreads();
#pragma unroll
    for (int mt = 0; mt < 2; mt++) {
        const int row = wm + 16 * mt + gid;
#pragma unroll
        for (int nt = 0; nt < 4; nt++) {
            const int col = wn + 8 * nt + 2 * tig;
            *reinterpret_cast<float2*>(OUT + row * S + col) =
                make_float2(res[mt][nt][0], res[mt][nt][1]);
            *reinterpret_cast<float2*>(OUT + (row + 8) * S + col) =
                make_float2(res[mt][nt][2], res[mt][nt][3]);
        }
    }
    if (KEEP) {
#pragma unroll
        for (int mt = 0; mt < 2; mt++)
#pragma unroll
            for (int nt = 0; nt < 4; nt++)
#pragma unroll
                for (int q = 0; q < 4; q++) ores[mt][nt][q] = res[mt][nt][q];
    }
    __syncthreads();
}

// bf16 ldmatrix step, 1 barrier. WB: bf16 smem out; WG: f32 gmem out (stride 64).
template<bool HAS_X, bool KEEP, bool WB, bool WG>
__device__ __forceinline__ void mm_bf16_ldm(
    const __nv_bfloat16* A, const __nv_bfloat16* Y,
    __nv_bfloat16* On, float* Og, float a, float s,
    const float (*xres)[4][4], float (*ores)[4][4]) {
    const int t = threadIdx.x, lane = t & 31, w = t >> 5;
    const int gid = lane >> 2, tig = lane & 3;
    const int wm = (w >> 1) * 32, wn = (w & 1) * 32;
    const int lr  = (lane & 7) + ((lane >> 3) & 1) * 8;
    const int lc8 = ((lane >> 4) & 1) * 8;

    const unsigned aB = smem_u32(A) + (unsigned)(((wm + lr) * SB2 + lc8) * 2);
    const unsigned bB = smem_u32(Y) + (unsigned)((lr * SB2 + wn + lc8) * 2);

    float acc[2][4][4];
#pragma unroll
    for (int mt = 0; mt < 2; mt++)
#pragma unroll
        for (int nt = 0; nt < 4; nt++)
#pragma unroll
            for (int q = 0; q < 4; q++) acc[mt][nt][q] = 0.f;

#pragma unroll
    for (int ks = 0; ks < 4; ks++) {
        unsigned af[2][4], bf_[2][4];
        ldm_x4(af[0], aB + ks * 32);
        ldm_x4(af[1], aB + 16 * SB2 * 2 + ks * 32);
        ldm_x4_t(bf_[0], bB + ks * 16 * SB2 * 2);
        ldm_x4_t(bf_[1], bB + 32 + ks * 16 * SB2 * 2);
#pragma unroll
        for (int mt = 0; mt < 2; mt++)
#pragma unroll
            for (int nt = 0; nt < 4; nt++)
                mma_bf16(acc[mt][nt], af[mt][0], af[mt][1], af[mt][2], af[mt][3],
                         bf_[nt >> 1][(nt & 1) * 2], bf_[nt >> 1][(nt & 1) * 2 + 1]);
    }

    float res[2][4][4];
#pragma unroll
    for (int mt = 0; mt < 2; mt++)
#pragma unroll
        for (int nt = 0; nt < 4; nt++)
#pragma unroll
            for (int q = 0; q < 4; q++) {
                float v = s * acc[mt][nt][q];
                if (HAS_X) v += a * xres[mt][nt][q];
                res[mt][nt][q] = v;
            }
#pragma unroll
    for (int mt = 0; mt < 2; mt++) {
        const int row = wm + 16 * mt + gid;
#pragma unroll
        for (int nt = 0; nt < 4; nt++) {
            const int col = wn + 8 * nt + 2 * tig;
            if (WB) {
                *reinterpret_cast<unsigned*>(On + row * SB2 + col) =
                    pack_bf16x2(res[mt][nt][0], res[mt][nt][1]);
                *reinterpret_cast<unsigned*>(On + (row + 8) * SB2 + col) =
                    pack_bf16x2(res[mt][nt][2], res[mt][nt][3]);
            }
            if (WG) {
                *reinterpret_cast<float2*>(Og + row * 64 + col) =
                    make_float2(res[mt][nt][0], res[mt][nt][1]);
                *reinterpret_cast<float2*>(Og + (row + 8) * 64 + col) =
                    make_float2(res[mt][nt][2], res[mt][nt][3]);
            }
        }
    }
    if (KEEP) {
#pragma unroll
        for (int mt = 0; mt < 2; mt++)
#pragma unroll
            for (int nt = 0; nt < 4; nt++)
#pragma unroll
                for (int q = 0; q < 4; q++) ores[mt][nt][q] = res[mt][nt][q];
    }
    __syncthreads();
}

// ---------------------------------------------------------------------------
// Kernel 1: gi = gi_latent @ W_up^T + b_up via EC-tf32 (proven R13)
// ---------------------------------------------------------------------------
__global__ __launch_bounds__(128) void k_up(const float* __restrict__ gi_latent,
                                            const float* __restrict__ W_up,
                                            const float* __restrict__ b_up) {
    __shared__ float sA[64 * S];
    __shared__ float sWt[64 * S];
    const int s0 = blockIdx.y * 64, g0 = blockIdx.x * 64, t = threadIdx.x;

    const float4* Ag = reinterpret_cast<const float4*>(gi_latent + s0 * 64);
#pragma unroll
    for (int q = 0; q < 8; q++) {
        int e = t + q * 128;
        int row = e >> 4, c4 = e & 15;
        *reinterpret_cast<float4*>(sA + row * S + c4 * 4) = Ag[e];
    }
#pragma unroll
    for (int q = 0; q < 8; q++) {
        int e = t + q * 128;
        int row = e >> 4, c4 = e & 15, g = g0 + row;
        float4 v = make_float4(0.f, 0.f, 0.f, 0.f);
        if (g < GDIM) v = reinterpret_cast<const float4*>(W_up + g * 64)[c4];
        sWt[(c4 * 4 + 0) * S + row] = v.x;
        sWt[(c4 * 4 + 1) * S + row] = v.y;
        sWt[(c4 * 4 + 2) * S + row] = v.z;
        sWt[(c4 * 4 + 3) * S + row] = v.w;
    }
    __syncthreads();

    const int lane = t & 31, w = t >> 5;
    const int gid = lane >> 2, tig = lane & 3;
    const int wm = (w >> 1) * 32, wn = (w & 1) * 32;

    float acc[2][4][4];
#pragma unroll
    for (int mt = 0; mt < 2; mt++)
#pragma unroll
        for (int nt = 0; nt < 4; nt++)
#pragma unroll
            for (int q = 0; q < 4; q++) acc[mt][nt][q] = 0.f;
    ec_accum(sA, sWt, acc, wm, wn, gid, tig);

#pragma unroll
    for (int mt = 0; mt < 2; mt++) {
        const int row = s0 + wm + 16 * mt + gid;
#pragma unroll
        for (int nt = 0; nt < 4; nt++) {
            const int col = g0 + wn + 8 * nt + 2 * tig;
            if (col < GDIM) {
                float2 bb = *reinterpret_cast<const float2*>(b_up + col);
                *reinterpret_cast<float2*>(g_gi + (size_t)row * GDIM + col) =
                    make_float2(acc[mt][nt][0] + bb.x, acc[mt][nt][1] + bb.y);
                *reinterpret_cast<float2*>(g_gi + (size_t)(row + 8) * GDIM + col) =
                    make_float2(acc[mt][nt][2] + bb.x, acc[mt][nt][3] + bb.y);
            }
        }
    }
}

// ---------------------------------------------------------------------------
// Kernel 2: bf16 NS iterations 1-9 ONLY. 55.4KB smem -> 4 CTAs/SM.
// Writes Z9 (f32) to g_z9.
// ---------------------------------------------------------------------------
__global__ __launch_bounds__(128, 4) void k_bf16(float* __restrict__ z9out) {
    extern __shared__ char smem_raw[];
    __nv_bfloat16* bB  = (__nv_bfloat16*)(smem_raw);
    __nv_bfloat16* bP  = (__nv_bfloat16*)(smem_raw + 1 * BMB);
    __nv_bfloat16* bU  = (__nv_bfloat16*)(smem_raw + 2 * BMB);
    __nv_bfloat16* bV  = (__nv_bfloat16*)(smem_raw + 3 * BMB);
    __nv_bfloat16* bZ0 = (__nv_bfloat16*)(smem_raw + 4 * BMB);
    __nv_bfloat16* bZ1 = (__nv_bfloat16*)(smem_raw + 5 * BMB);
    float* sred = (float*)(smem_raw + 6 * BMB);

    const int n = blockIdx.x, t = threadIdx.x;
    const float* gi = g_gi + (size_t)n * GDIM;

    // pass 1: gi -> registers, build bB, accumulate norm terms
    float gv[16];
    int   gi_i[16], gi_j[16];
    float lsum = 0.f, lmax = 0.f;
#pragma unroll
    for (int q = 0; q < 16; q++) {
        int e = t + q * 128;
        gv[q] = 0.f; gi_i[q] = 0; gi_j[q] = 0;
        if (e < GDIM) {
            int i = (int)((1.0f + sqrtf(1.0f + 8.0f * (float)e)) * 0.5f);
            while (i * (i - 1) / 2 > e) i--;
            while ((i + 1) * i / 2 <= e) i++;
            int j = e - i * (i - 1) / 2;
            float v = gi[e];
            gv[q] = v; gi_i[q] = i; gi_j[q] = j;
            bB[i * SB2 + j] = __float2bfloat16(v);
            bB[j * SB2 + i] = __float2bfloat16(-v);
            float av = fabsf(v);
            lsum += av;
            lmax = fmaxf(lmax, av);
        }
    }
    if (t < 64) bB[t * SB2 + t] = __float2bfloat16(1.0f);
#pragma unroll
    for (int o = 16; o; o >>= 1) {
        lsum += __shfl_xor_sync(0xFFFFFFFFu, lsum, o);
        lmax = fmaxf(lmax, __shfl_xor_sync(0xFFFFFFFFu, lmax, o));
    }
    if ((t & 31) == 0) { sred[t >> 5] = lsum; sred[4 + (t >> 5)] = lmax; }
    __syncthreads();
    if (t == 0) {
        float Sm = 64.0f + 2.0f * (sred[0] + sred[1] + sred[2] + sred[3]);
        float Mx = fmaxf(1.0f, fmaxf(fmaxf(sred[4], sred[5]), fmaxf(sred[6], sred[7])));
        sred[8] = 1.0f / (Sm * Mx);
    }
    __syncthreads();
    const float invn = sred[8];

    // pass 2: bZ0 = bf16(B^T * invn), from registers
#pragma unroll
    for (int q = 0; q < 16; q++) {
        if (t + q * 128 < GDIM) {
            int i = gi_i[q], j = gi_j[q];
            float v = gv[q] * invn;
            bZ0[j * SB2 + i] = __float2bfloat16(v);
            bZ0[i * SB2 + j] = __float2bfloat16(-v);
        }
    }
    if (t < 64) bZ0[t * SB2 + t] = __float2bfloat16(invn);
    __syncthreads();

    // Zres from bZ0 (bf16 precision is fine for the bf16 phase)
    float Pres[2][4][4], Zres[2][4][4];
    {
        const int lane = t & 31, w = t >> 5;
        const int gid = lane >> 2, tig = lane & 3;
        const int wm = (w >> 1) * 32, wn = (w & 1) * 32;
#pragma unroll
        for (int mt = 0; mt < 2; mt++) {
            const int row = wm + 16 * mt + gid;
#pragma unroll
            for (int nt = 0; nt < 4; nt++) {
                const int col = wn + 8 * nt + 2 * tig;
                Zres[mt][nt][0] = __bfloat162float(bZ0[row * SB2 + col]);
                Zres[mt][nt][1] = __bfloat162float(bZ0[row * SB2 + col + 1]);
                Zres[mt][nt][2] = __bfloat162float(bZ0[(row + 8) * SB2 + col]);
                Zres[mt][nt][3] = __bfloat162float(bZ0[(row + 8) * SB2 + col + 1]);
            }
        }
    }

    // iterations 1..8: ping-pong
#pragma unroll 1
    for (int it = 0; it < 8; it++) {
        __nv_bfloat16* Zc = (it & 1) ? bZ1 : bZ0;
        __nv_bfloat16* Zn = (it & 1) ? bZ0 : bZ1;
        mm_bf16_ldm<false, true,  true,  false>(bB, Zc, bP, nullptr, 0.f, 1.f, nullptr, Pres);
        mm_bf16_ldm<true,  false, true,  false>(bP, bP, bU, nullptr, 7.f, -1.f, Pres, nullptr);
        mm_bf16_ldm<true,  false, true,  false>(bP, bU, bV, nullptr, 15.f, -1.f, Pres, nullptr);
        mm_bf16_ldm<true,  true,  true,  false>(Zc, bV, Zn, nullptr, 3.25f, -0.25f, Zres, Zres);
    }
    // iteration 9: last step writes f32 Z9 to gmem
    mm_bf16_ldm<false, true,  true,  false>(bB, bZ0, bP, nullptr, 0.f, 1.f, nullptr, Pres);
    mm_bf16_ldm<true,  false, true,  false>(bP, bP, bU, nullptr, 7.f, -1.f, Pres, nullptr);
    mm_bf16_ldm<true,  false, true,  false>(bP, bU, bV, nullptr, 15.f, -1.f, Pres, nullptr);
    mm_bf16_ldm<true,  false, false, true >(bZ0, bV, nullptr, z9out + (size_t)n * 4096,
                                            3.25f, -0.25f, Zres, nullptr);
}

// ---------------------------------------------------------------------------
// Kernel 3: EC-tf32 iteration 10 + R + MLP tail. 70.9KB smem -> 3 CTAs/SM.
// ---------------------------------------------------------------------------
__global__ __launch_bounds__(128, 3) void k_ec(
    const float* __restrict__ li_latent, const float* __restrict__ z9in,
    const float* __restrict__ W1, const float* __restrict__ b1,
    const float* __restrict__ W2, const float* __restrict__ b2,
    const float* __restrict__ W3, const float* __restrict__ b3,
    const float* __restrict__ W4, const float* __restrict__ b4,
    const float* __restrict__ W5, const float* __restrict__ b5,
    const float* __restrict__ W6, const float* __restrict__ b6,
    float* __restrict__ out) {
    extern __shared__ float smem[];
    float* sB = smem;
    float* sZ = smem + MS;
    float* sP = smem + 2 * MS;
    float* sU = smem + 3 * MS;
    float* sv = smem + 4 * MS;

    const int n = blockIdx.x, t = threadIdx.x;
    const float* gi = g_gi + (size_t)n * GDIM;

    // rebuild B (f32)
    for (int e = t; e < GDIM; e += 128) {
        int i = (int)((1.0f + sqrtf(1.0f + 8.0f * (float)e)) * 0.5f);
        while (i * (i - 1) / 2 > e) i--;
        while ((i + 1) * i / 2 <= e) i++;
        int j = e - i * (i - 1) / 2;
        float v = gi[e];
        sB[i * S + j] = v;
        sB[j * S + i] = -v;
    }
    if (t < 64) sB[t * S + t] = 1.0f;
    // load Z9
    {
        const float4* zp = reinterpret_cast<const float4*>(z9in + (size_t)n * 4096);
#pragma unroll
        for (int q = 0; q < 8; q++) {
            int e = t + q * 128;            // float4 index over 64x16
            int row = e >> 4, c4 = e & 15;
            *reinterpret_cast<float4*>(sZ + row * S + c4 * 4) = zp[e];
        }
    }
    __syncthreads();

    float Pres[2][4][4], Zres[2][4][4];
    {
        const int lane = t & 31, w = t >> 5;
        const int gid = lane >> 2, tig = lane & 3;
        const int wm = (w >> 1) * 32, wn = (w & 1) * 32;
#pragma unroll
        for (int mt = 0; mt < 2; mt++) {
            const int row = wm + 16 * mt + gid;
#pragma unroll
            for (int nt = 0; nt < 4; nt++) {
                const int col = wn + 8 * nt + 2 * tig;
                float2 x0 = *reinterpret_cast<const float2*>(sZ + row * S + col);
                float2 x1 = *reinterpret_cast<const float2*>(sZ + (row + 8) * S + col);
                Zres[mt][nt][0] = x0.x; Zres[mt][nt][1] = x0.y;
                Zres[mt][nt][2] = x1.x; Zres[mt][nt][3] = x1.y;
            }
        }
    }

    mm_ec_step<false, true,  false>(sB, sZ, sP, 0.0f,  1.0f,  nullptr, Pres);
    mm_ec_step<true,  false, false>(sP, sP, sU, 7.0f,  -1.0f, Pres, nullptr);
    mm_ec_step<true,  false, true >(sP, sU, sU, 15.0f, -1.0f, Pres, nullptr);
    mm_ec_step<true,  true,  true >(sZ, sU, sZ, 3.25f, -0.25f, Zres, Zres);
    mm_ec_step<true,  false, false>(sZ, sB, sP, 2.0f, -1.0f, Zres, nullptr);  // R
    const float* R = sP;

    // MLP tail
    if (t < 64) sv[t] = li_latent[n * 64 + t];
    __syncthreads();
    if (t < 64) {
        float acc = 0.f;
        for (int i = 0; i < 64; i++) acc += R[i * S + t] * sv[i];
        sv[64 + t] = acc;
    }
    __syncthreads();
    if (t < 64) {
        float acc = b1[t];
        const float* w = W1 + t * 64;
        for (int k = 0; k < 64; k++) acc += sv[64 + k] * w[k];
        sv[128 + t] = fmaxf(acc, 0.f);
    }
    __syncthreads();
    if (t < 64) {
        float acc = b2[t];
        const float* w = W2 + t * 64;
        for (int k = 0; k < 64; k++) acc += sv[128 + k] * w[k];
        sv[192 + t] = acc;
    }
    __syncthreads();
    if (t < 64) {
        float acc = 0.f;
        for (int jj = 0; jj < 64; jj++) {
            int j = (t + jj) & 63;
            acc += R[t * S + j] * sv[192 + j];
        }
        sv[64 + t] = acc;
        out[262144 + 8192 + n * 64 + t] = acc;
    }
    __syncthreads();
    if (t < 64) {
        float acc = b3[t];
        const float* w = W3 + t * 64;
        for (int k = 0; k < 64; k++) acc += sv[64 + k] * w[k];
        sv[128 + t] = fmaxf(acc, 0.f);
    }
    __syncthreads();
    if (t < 64) {
        float acc = b4[t];
        const float* w = W4 + t * 64;
        for (int j = 0; j < 64; j++) acc += sv[128 + j] * w[j];
        out[n * 64 + t] = acc;

        float acc5 = b5[t];
        const float* w5 = W5 + t * 64;
        for (int k = 0; k < 64; k++) acc5 += sv[64 + k] * w5[k];
        sv[192 + t] = fmaxf(acc5, 0.f);
    }
    __syncthreads();
    if (t < 2) {
        float acc = b6[t];
        const float* w = W6 + t * 64;
        for (int j = 0; j < 64; j++) acc += sv[192 + j] * w[j];
        out[262144 + n * 2 + t] = acc;
    }
}

extern "C" void kernel_launch(void* const* d_in, const int* in_sizes, int n_in,
                              void* d_out, int out_size) {
    const float* li   = (const float*)d_in[0];
    const float* gl   = (const float*)d_in[1];
    const float* W_up = (const float*)d_in[2];
    const float* b_up = (const float*)d_in[3];
    const float* W1 = (const float*)d_in[4];
    const float* b1 = (const float*)d_in[5];
    const float* W2 = (const float*)d_in[6];
    const float* b2 = (const float*)d_in[7];
    const float* W3 = (const float*)d_in[8];
    const float* b3 = (const float*)d_in[9];
    const float* W4 = (const float*)d_in[10];
    const float* b4 = (const float*)d_in[11];
    const float* W5 = (const float*)d_in[12];
    const float* b5 = (const float*)d_in[13];
    const float* W6 = (const float*)d_in[14];
    const float* b6 = (const float*)d_in[15];
    float* out = (float*)d_out;

    cudaFuncSetAttribute(k_bf16, cudaFuncAttributeMaxDynamicSharedMemorySize,
                         (int)KM_SMEM_BYTES);
    cudaFuncSetAttribute(k_ec, cudaFuncAttributeMaxDynamicSharedMemorySize,
                         (int)KE_SMEM_BYTES);

    float* z9;
    cudaGetSymbolAddress((void**)&z9, g_z9);

    k_up<<<dim3(32, NB / 64), 128>>>(gl, W_up, b_up);
    k_bf16<<<NB, 128, KM_SMEM_BYTES>>>(z9);
    k_ec<<<NB, 128, KE_SMEM_BYTES>>>(li, z9, W1, b1, W2, b2, W3, b3, W4, b4,
                                     W5, b5, W6, b6, out);
}

// round 15
// speedup vs baseline: 1.1707x; 1.1707x over previous
#include <cuda_runtime.h>
#include <cuda_bf16.h>

#define NB    4096
#define GDIM  2016
#define S     68
#define MS    (64 * S)          // 4352 floats = 17408 B
#define SB2   72                // bf16 row stride (elements), 144 B
#define RXF   13824             // floats in region X (55296 B)
#define MAIN_SMEM_FLOATS (MS + RXF + 256 + 32)
#define MAIN_SMEM_BYTES  (MAIN_SMEM_FLOATS * sizeof(float))

__device__ float g_gi[NB * GDIM];

__device__ __forceinline__ unsigned f2tf32_rna(float f) {
    unsigned u;
    asm("cvt.rna.tf32.f32 %0, %1;" : "=r"(u) : "f"(f));
    return u;
}
__device__ __forceinline__ unsigned pack_bf16x2(float lo, float hi) {
    unsigned u;
    asm("cvt.rn.bf16x2.f32 %0, %1, %2;" : "=r"(u) : "f"(hi), "f"(lo));
    return u;
}
__device__ __forceinline__ unsigned smem_u32(const void* p) {
    return (unsigned)__cvta_generic_to_shared(p);
}
__device__ __forceinline__ void ldm_x4(unsigned* r, unsigned addr) {
    asm volatile("ldmatrix.sync.aligned.m8n8.x4.shared.b16 {%0,%1,%2,%3}, [%4];"
                 : "=r"(r[0]), "=r"(r[1]), "=r"(r[2]), "=r"(r[3]) : "r"(addr));
}
__device__ __forceinline__ void ldm_x4_t(unsigned* r, unsigned addr) {
    asm volatile("ldmatrix.sync.aligned.m8n8.x4.trans.shared.b16 {%0,%1,%2,%3}, [%4];"
                 : "=r"(r[0]), "=r"(r[1]), "=r"(r[2]), "=r"(r[3]) : "r"(addr));
}
__device__ __forceinline__ void mma_tf32(float* c, unsigned a0, unsigned a1,
                                         unsigned a2, unsigned a3,
                                         unsigned b0, unsigned b1) {
    asm volatile(
        "mma.sync.aligned.m16n8k8.row.col.f32.tf32.tf32.f32 "
        "{%0,%1,%2,%3}, {%4,%5,%6,%7}, {%8,%9}, {%0,%1,%2,%3};"
        : "+f"(c[0]), "+f"(c[1]), "+f"(c[2]), "+f"(c[3])
        : "r"(a0), "r"(a1), "r"(a2), "r"(a3), "r"(b0), "r"(b1));
}
__device__ __forceinline__ void mma_bf16(float* c, unsigned a0, unsigned a1,
                                         unsigned a2, unsigned a3,
                                         unsigned b0, unsigned b1) {
    asm volatile(
        "mma.sync.aligned.m16n8k16.row.col.f32.bf16.bf16.f32 "
        "{%0,%1,%2,%3}, {%4,%5,%6,%7}, {%8,%9}, {%0,%1,%2,%3};"
        : "+f"(c[0]), "+f"(c[1]), "+f"(c[2]), "+f"(c[3])
        : "r"(a0), "r"(a1), "r"(a2), "r"(a3), "r"(b0), "r"(b1));
}

// EC-tf32 core: acc += X@Y at fp32 quality (3 mma). X,Y f32 stride-S.
__device__ __forceinline__ void ec_accum(const float* X, const float* Y,
                                         float (*acc)[4][4],
                                         int wm, int wn, int gid, int tig) {
#pragma unroll
    for (int ks = 0; ks < 8; ks++) {
        const int k0 = ks * 8;
        float a_f[2][4], b_f[4][2];
#pragma unroll
        for (int mt = 0; mt < 2; mt++) {
            const float* ap = X + (wm + 16 * mt + gid) * S + k0 + tig;
            a_f[mt][0] = ap[0]; a_f[mt][1] = ap[8 * S];
            a_f[mt][2] = ap[4]; a_f[mt][3] = ap[8 * S + 4];
        }
#pragma unroll
        for (int nt = 0; nt < 4; nt++) {
            const float* bp = Y + (k0 + tig) * S + wn + 8 * nt + gid;
            b_f[nt][0] = bp[0]; b_f[nt][1] = bp[4 * S];
        }
        unsigned ahi[2][4], alo[2][4], bhi[4][2], blo[4][2];
#pragma unroll
        for (int mt = 0; mt < 2; mt++)
#pragma unroll
            for (int q = 0; q < 4; q++) {
                float x = a_f[mt][q]; unsigned h = f2tf32_rna(x);
                ahi[mt][q] = h; alo[mt][q] = __float_as_uint(x - __uint_as_float(h));
            }
#pragma unroll
        for (int nt = 0; nt < 4; nt++)
#pragma unroll
            for (int q = 0; q < 2; q++) {
                float x = b_f[nt][q]; unsigned h = f2tf32_rna(x);
                bhi[nt][q] = h; blo[nt][q] = __float_as_uint(x - __uint_as_float(h));
            }
#pragma unroll
        for (int mt = 0; mt < 2; mt++)
#pragma unroll
            for (int nt = 0; nt < 4; nt++) {
                mma_tf32(acc[mt][nt], ahi[mt][0], ahi[mt][1], ahi[mt][2], ahi[mt][3],
                         blo[nt][0], blo[nt][1]);
                mma_tf32(acc[mt][nt], alo[mt][0], alo[mt][1], alo[mt][2], alo[mt][3],
                         bhi[nt][0], bhi[nt][1]);
                mma_tf32(acc[mt][nt], ahi[mt][0], ahi[mt][1], ahi[mt][2], ahi[mt][3],
                         bhi[nt][0], bhi[nt][1]);
            }
    }
}

// EC-tf32 step: OUT = s*(X@Y) + a*xres. OUT must not alias a live input
// (all EC calls below write to dead buffers -> no presync needed).
template<bool HAS_X, bool KEEP>
__device__ __forceinline__ void mm_ec_step(const float* X, const float* Y,
                                           float* OUT, float a, float s,
                                           const float (*xres)[4][4],
                                           float (*ores)[4][4]) {
    const int t = threadIdx.x, lane = t & 31, w = t >> 5;
    const int gid = lane >> 2, tig = lane & 3;
    const int wm = (w >> 1) * 32, wn = (w & 1) * 32;

    float acc[2][4][4];
#pragma unroll
    for (int mt = 0; mt < 2; mt++)
#pragma unroll
        for (int nt = 0; nt < 4; nt++)
#pragma unroll
            for (int q = 0; q < 4; q++) acc[mt][nt][q] = 0.f;
    ec_accum(X, Y, acc, wm, wn, gid, tig);

    float res[2][4][4];
#pragma unroll
    for (int mt = 0; mt < 2; mt++)
#pragma unroll
        for (int nt = 0; nt < 4; nt++)
#pragma unroll
            for (int q = 0; q < 4; q++) {
                float v = s * acc[mt][nt][q];
                if (HAS_X) v += a * xres[mt][nt][q];
                res[mt][nt][q] = v;
            }
#pragma unroll
    for (int mt = 0; mt < 2; mt++) {
        const int row = wm + 16 * mt + gid;
#pragma unroll
        for (int nt = 0; nt < 4; nt++) {
            const int col = wn + 8 * nt + 2 * tig;
            *reinterpret_cast<float2*>(OUT + row * S + col) =
                make_float2(res[mt][nt][0], res[mt][nt][1]);
            *reinterpret_cast<float2*>(OUT + (row + 8) * S + col) =
                make_float2(res[mt][nt][2], res[mt][nt][3]);
        }
    }
    if (KEEP) {
#pragma unroll
        for (int mt = 0; mt < 2; mt++)
#pragma unroll
            for (int nt = 0; nt < 4; nt++)
#pragma unroll
                for (int q = 0; q < 4; q++) ores[mt][nt][q] = res[mt][nt][q];
    }
    __syncthreads();
}

// bf16 ldmatrix step, SINGLE barrier: OUT never aliases a live-read buffer.
template<bool HAS_X, bool KEEP, bool WB, bool WF>
__device__ __forceinline__ void mm_bf16_ldm(
    const __nv_bfloat16* A, const __nv_bfloat16* Y,
    __nv_bfloat16* On, float* Of, float a, float s,
    const float (*xres)[4][4], float (*ores)[4][4]) {
    const int t = threadIdx.x, lane = t & 31, w = t >> 5;
    const int gid = lane >> 2, tig = lane & 3;
    const int wm = (w >> 1) * 32, wn = (w & 1) * 32;
    const int lr  = (lane & 7) + ((lane >> 3) & 1) * 8;
    const int lc8 = ((lane >> 4) & 1) * 8;

    const unsigned aB = smem_u32(A) + (unsigned)(((wm + lr) * SB2 + lc8) * 2);
    const unsigned bB = smem_u32(Y) + (unsigned)((lr * SB2 + wn + lc8) * 2);

    float acc[2][4][4];
#pragma unroll
    for (int mt = 0; mt < 2; mt++)
#pragma unroll
        for (int nt = 0; nt < 4; nt++)
#pragma unroll
            for (int q = 0; q < 4; q++) acc[mt][nt][q] = 0.f;

#pragma unroll
    for (int ks = 0; ks < 4; ks++) {
        unsigned af[2][4], bf_[2][4];
        ldm_x4(af[0], aB + ks * 32);
        ldm_x4(af[1], aB + 16 * SB2 * 2 + ks * 32);
        ldm_x4_t(bf_[0], bB + ks * 16 * SB2 * 2);
        ldm_x4_t(bf_[1], bB + 32 + ks * 16 * SB2 * 2);
#pragma unroll
        for (int mt = 0; mt < 2; mt++)
#pragma unroll
            for (int nt = 0; nt < 4; nt++)
                mma_bf16(acc[mt][nt], af[mt][0], af[mt][1], af[mt][2], af[mt][3],
                         bf_[nt >> 1][(nt & 1) * 2], bf_[nt >> 1][(nt & 1) * 2 + 1]);
    }

    float res[2][4][4];
#pragma unroll
    for (int mt = 0; mt < 2; mt++)
#pragma unroll
        for (int nt = 0; nt < 4; nt++)
#pragma unroll
            for (int q = 0; q < 4; q++) {
                float v = s * acc[mt][nt][q];
                if (HAS_X) v += a * xres[mt][nt][q];
                res[mt][nt][q] = v;
            }
#pragma unroll
    for (int mt = 0; mt < 2; mt++) {
        const int row = wm + 16 * mt + gid;
#pragma unroll
        for (int nt = 0; nt < 4; nt++) {
            const int col = wn + 8 * nt + 2 * tig;
            if (WB) {
                *reinterpret_cast<unsigned*>(On + row * SB2 + col) =
                    pack_bf16x2(res[mt][nt][0], res[mt][nt][1]);
                *reinterpret_cast<unsigned*>(On + (row + 8) * SB2 + col) =
                    pack_bf16x2(res[mt][nt][2], res[mt][nt][3]);
            }
            if (WF) {
                *reinterpret_cast<float2*>(Of + row * S + col) =
                    make_float2(res[mt][nt][0], res[mt][nt][1]);
                *reinterpret_cast<float2*>(Of + (row + 8) * S + col) =
                    make_float2(res[mt][nt][2], res[mt][nt][3]);
            }
        }
    }
    if (KEEP) {
#pragma unroll
        for (int mt = 0; mt < 2; mt++)
#pragma unroll
            for (int nt = 0; nt < 4; nt++)
#pragma unroll
                for (int q = 0; q < 4; q++) ores[mt][nt][q] = res[mt][nt][q];
    }
    __syncthreads();
}

// ---------------------------------------------------------------------------
// Kernel 1: gi = gi_latent @ W_up^T + b_up via EC-tf32 (proven R13)
// ---------------------------------------------------------------------------
__global__ __launch_bounds__(128) void k_up(const float* __restrict__ gi_latent,
                                            const float* __restrict__ W_up,
                                            const float* __restrict__ b_up) {
    __shared__ float sA[64 * S];
    __shared__ float sWt[64 * S];
    const int s0 = blockIdx.y * 64, g0 = blockIdx.x * 64, t = threadIdx.x;

    const float4* Ag = reinterpret_cast<const float4*>(gi_latent + s0 * 64);
#pragma unroll
    for (int q = 0; q < 8; q++) {
        int e = t + q * 128;
        int row = e >> 4, c4 = e & 15;
        *reinterpret_cast<float4*>(sA + row * S + c4 * 4) = Ag[e];
    }
#pragma unroll
    for (int q = 0; q < 8; q++) {
        int e = t + q * 128;
        int row = e >> 4, c4 = e & 15, g = g0 + row;
        float4 v = make_float4(0.f, 0.f, 0.f, 0.f);
        if (g < GDIM) v = reinterpret_cast<const float4*>(W_up + g * 64)[c4];
        sWt[(c4 * 4 + 0) * S + row] = v.x;
        sWt[(c4 * 4 + 1) * S + row] = v.y;
        sWt[(c4 * 4 + 2) * S + row] = v.z;
        sWt[(c4 * 4 + 3) * S + row] = v.w;
    }
    __syncthreads();

    const int lane = t & 31, w = t >> 5;
    const int gid = lane >> 2, tig = lane & 3;
    const int wm = (w >> 1) * 32, wn = (w & 1) * 32;

    float acc[2][4][4];
#pragma unroll
    for (int mt = 0; mt < 2; mt++)
#pragma unroll
        for (int nt = 0; nt < 4; nt++)
#pragma unroll
            for (int q = 0; q < 4; q++) acc[mt][nt][q] = 0.f;
    ec_accum(sA, sWt, acc, wm, wn, gid, tig);

#pragma unroll
    for (int mt = 0; mt < 2; mt++) {
        const int row = s0 + wm + 16 * mt + gid;
#pragma unroll
        for (int nt = 0; nt < 4; nt++) {
            const int col = g0 + wn + 8 * nt + 2 * tig;
            if (col < GDIM) {
                float2 bb = *reinterpret_cast<const float2*>(b_up + col);
                *reinterpret_cast<float2*>(g_gi + (size_t)row * GDIM + col) =
                    make_float2(acc[mt][nt][0] + bb.x, acc[mt][nt][1] + bb.y);
                *reinterpret_cast<float2*>(g_gi + (size_t)(row + 8) * GDIM + col) =
                    make_float2(acc[mt][nt][2] + bb.x, acc[mt][nt][3] + bb.y);
            }
        }
    }
}

// ---------------------------------------------------------------------------
// Kernel 2: per-sample Cayley + MLP. bf16 iters 1-9 (ping-pong, 1 bar/step),
// then Newton cleanup + R in EC-tf32 (3 steps, no presyncs).
// ---------------------------------------------------------------------------
__global__ __launch_bounds__(128, 3) void k_main(
    const float* __restrict__ li_latent,
    const float* __restrict__ W1, const float* __restrict__ b1,
    const float* __restrict__ W2, const float* __restrict__ b2,
    const float* __restrict__ W3, const float* __restrict__ b3,
    const float* __restrict__ W4, const float* __restrict__ b4,
    const float* __restrict__ W5, const float* __restrict__ b5,
    const float* __restrict__ W6, const float* __restrict__ b6,
    float* __restrict__ out) {
    extern __shared__ float smem[];
    float* sB = smem;                       // f32 B, never aliased
    char*  rx = (char*)(smem + MS);         // 55296-byte region X
    __nv_bfloat16* bB  = (__nv_bfloat16*)(rx);            //     0.. 9216
    __nv_bfloat16* bP  = (__nv_bfloat16*)(rx +  9216);    //  9216..18432
    __nv_bfloat16* bU  = (__nv_bfloat16*)(rx + 18432);    // 18432..27648
    __nv_bfloat16* bV  = (__nv_bfloat16*)(rx + 27648);    // 27648..36864
    __nv_bfloat16* bZ0 = (__nv_bfloat16*)(rx + 36864);    // 36864..46080
    __nv_bfloat16* bZ1 = (__nv_bfloat16*)(rx + 46080);    // 46080..55296
    // f32 overlay (each region written only after the bf16 buffers it covers
    // are dead):
    float* sZ = (float*)(rx);                             //     0..17408 (bB,bP)
    float* sP = (float*)(rx + 17408);                     // 17408..34816 (bU,bV)
    float* sU = (float*)(rx + 34816);                     // 34816..52224 (bZ0,bZ1)
    float* sv   = smem + MS + RXF;
    float* sred = smem + MS + RXF + 256;

    const int n = blockIdx.x, t = threadIdx.x;
    const float* gi = g_gi + (size_t)n * GDIM;

    for (int e = t; e < GDIM; e += 128) {
        int i = (int)((1.0f + sqrtf(1.0f + 8.0f * (float)e)) * 0.5f);
        while (i * (i - 1) / 2 > e) i--;
        while ((i + 1) * i / 2 <= e) i++;
        int j = e - i * (i - 1) / 2;
        float v = gi[e];
        sB[i * S + j] = v;
        sB[j * S + i] = -v;
    }
    if (t < 64) sB[t * S + t] = 1.0f;
    __syncthreads();

    {
        const int r = t >> 1, c0 = (t & 1) * 32;
        float lsum = 0.f, lmax = 0.f;
#pragma unroll
        for (int q = 0; q < 8; q++) {
            float4 v = *reinterpret_cast<const float4*>(sB + r * S + c0 + q * 4);
            lsum += fabsf(v.x) + fabsf(v.y) + fabsf(v.z) + fabsf(v.w);
            lmax = fmaxf(lmax, fmaxf(fmaxf(fabsf(v.x), fabsf(v.y)),
                                     fmaxf(fabsf(v.z), fabsf(v.w))));
        }
#pragma unroll
        for (int o = 16; o; o >>= 1) {
            lsum += __shfl_xor_sync(0xFFFFFFFFu, lsum, o);
            lmax = fmaxf(lmax, __shfl_xor_sync(0xFFFFFFFFu, lmax, o));
        }
        if ((t & 31) == 0) { sred[t >> 5] = lsum; sred[4 + (t >> 5)] = lmax; }
    }
    __syncthreads();
    if (t == 0) {
        float Sm = sred[0] + sred[1] + sred[2] + sred[3];
        float Mx = fmaxf(fmaxf(sred[4], sred[5]), fmaxf(sred[6], sred[7]));
        sred[8] = 1.0f / (Sm * Mx);
    }
    __syncthreads();
    const float invn = sred[8];

    for (int e = t; e < 4096; e += 128) {
        int r = e >> 6, c = e & 63;
        float v = sB[r * S + c];
        bB[r * SB2 + c]  = __float2bfloat16(v);
        bZ0[c * SB2 + r] = __float2bfloat16(v * invn);   // Z0 row-major
    }
    __syncthreads();

    float Pres[2][4][4], Zres[2][4][4];
    {
        const int lane = t & 31, w = t >> 5;
        const int gid = lane >> 2, tig = lane & 3;
        const int wm = (w >> 1) * 32, wn = (w & 1) * 32;
#pragma unroll
        for (int mt = 0; mt < 2; mt++) {
            const int row = wm + 16 * mt + gid;
#pragma unroll
            for (int nt = 0; nt < 4; nt++) {
                const int col = wn + 8 * nt + 2 * tig;
                Zres[mt][nt][0] = sB[col * S + row] * invn;
                Zres[mt][nt][1] = sB[(col + 1) * S + row] * invn;
                Zres[mt][nt][2] = sB[col * S + row + 8] * invn;
                Zres[mt][nt][3] = sB[(col + 1) * S + row + 8] * invn;
            }
        }
    }

    // iterations 1..8: bf16 ping-pong, 1 barrier/step
#pragma unroll 1
    for (int it = 0; it < 8; it++) {
        __nv_bfloat16* Zc = (it & 1) ? bZ1 : bZ0;
        __nv_bfloat16* Zn = (it & 1) ? bZ0 : bZ1;
        mm_bf16_ldm<false, true,  true,  false>(bB, Zc, bP, nullptr, 0.f, 1.f, nullptr, Pres);
        mm_bf16_ldm<true,  false, true,  false>(bP, bP, bU, nullptr, 7.f, -1.f, Pres, nullptr);
        mm_bf16_ldm<true,  false, true,  false>(bP, bU, bV, nullptr, 15.f, -1.f, Pres, nullptr);
        mm_bf16_ldm<true,  true,  true,  false>(Zc, bV, Zn, nullptr, 3.25f, -0.25f, Zres, Zres);
    }
    // iteration 9: bf16 (Zc = bZ0), last step -> f32 sZ (overlays dead bB/bP
    // only AFTER the final reads of bB in this iteration's step 1)
    mm_bf16_ldm<false, true,  true,  false>(bB, bZ0, bP, nullptr, 0.f, 1.f, nullptr, Pres);
    mm_bf16_ldm<true,  false, true,  false>(bP, bP, bU, nullptr, 7.f, -1.f, Pres, nullptr);
    mm_bf16_ldm<true,  false, true,  false>(bP, bU, bV, nullptr, 15.f, -1.f, Pres, nullptr);
    mm_bf16_ldm<true,  true,  false, true >(bZ0, bV, nullptr, sZ, 3.25f, -0.25f, Zres, Zres);

    // Newton cleanup + R in EC-tf32 (fp32 quality), zero presyncs:
    //   P  = B @ Z9          -> sP  (overlays dead bU/bV)
    //   Zn = 2*Z9 - Z9 @ P   -> sU  (overlays dead bZ0/bZ1)   [E -> E^2]
    //   R  = 2*Zn - Zn @ B   -> sP  (P dead after previous step)
    mm_ec_step<false, false>(sB, sZ, sP, 0.0f, 1.0f, nullptr, nullptr);
    mm_ec_step<true,  true >(sZ, sP, sU, 2.0f, -1.0f, Zres, Zres);
    mm_ec_step<true,  false>(sU, sB, sP, 2.0f, -1.0f, Zres, nullptr);
    const float* R = sP;

    // MLP tail
    if (t < 64) sv[t] = li_latent[n * 64 + t];
    __syncthreads();
    if (t < 64) {
        float acc = 0.f;
        for (int i = 0; i < 64; i++) acc += R[i * S + t] * sv[i];
        sv[64 + t] = acc;
    }
    __syncthreads();
    if (t < 64) {
        float acc = b1[t];
        const float* w = W1 + t * 64;
        for (int k = 0; k < 64; k++) acc += sv[64 + k] * w[k];
        sv[128 + t] = fmaxf(acc, 0.f);
    }
    __syncthreads();
    if (t < 64) {
        float acc = b2[t];
        const float* w = W2 + t * 64;
        for (int k = 0; k < 64; k++) acc += sv[128 + k] * w[k];
        sv[192 + t] = acc;
    }
    __syncthreads();
    if (t < 64) {
        float acc = 0.f;
        for (int jj = 0; jj < 64; jj++) {
            int j = (t + jj) & 63;
            acc += R[t * S + j] * sv[192 + j];
        }
        sv[64 + t] = acc;
        out[262144 + 8192 + n * 64 + t] = acc;
    }
    __syncthreads();
    if (t < 64) {
        float acc = b3[t];
        const float* w = W3 + t * 64;
        for (int k = 0; k < 64; k++) acc += sv[64 + k] * w[k];
        sv[128 + t] = fmaxf(acc, 0.f);
    }
    __syncthreads();
    if (t < 64) {
        float acc = b4[t];
        const float* w = W4 + t * 64;
        for (int j = 0; j < 64; j++) acc += sv[128 + j] * w[j];
        out[n * 64 + t] = acc;

        float acc5 = b5[t];
        const float* w5 = W5 + t * 64;
        for (int k = 0; k < 64; k++) acc5 += sv[64 + k] * w5[k];
        sv[192 + t] = fmaxf(acc5, 0.f);
    }
    __syncthreads();
    if (t < 2) {
        float acc = b6[t];
        const float* w = W6 + t * 64;
        for (int j = 0; j < 64; j++) acc += sv[192 + j] * w[j];
        out[262144 + n * 2 + t] = acc;
    }
}

extern "C" void kernel_launch(void* const* d_in, const int* in_sizes, int n_in,
                              void* d_out, int out_size) {
    const float* li   = (const float*)d_in[0];
    const float* gl   = (const float*)d_in[1];
    const float* W_up = (const float*)d_in[2];
    const float* b_up = (const float*)d_in[3];
    const float* W1 = (const float*)d_in[4];
    const float* b1 = (const float*)d_in[5];
    const float* W2 = (const float*)d_in[6];
    const float* b2 = (const float*)d_in[7];
    const float* W3 = (const float*)d_in[8];
    const float* b3 = (const float*)d_in[9];
    const float* W4 = (const float*)d_in[10];
    const float* b4 = (const float*)d_in[11];
    const float* W5 = (const float*)d_in[12];
    const float* b5 = (const float*)d_in[13];
    const float* W6 = (const float*)d_in[14];
    const float* b6 = (const float*)d_in[15];
    float* out = (float*)d_out;

    cudaFuncSetAttribute(k_main, cudaFuncAttributeMaxDynamicSharedMemorySize,
                         (int)MAIN_SMEM_BYTES);

    k_up<<<dim3(32, NB / 64), 128>>>(gl, W_up, b_up);
    k_main<<<NB, 128, MAIN_SMEM_BYTES>>>(li, W1, b1, W2, b2, W3, b3, W4, b4,
                                         W5, b5, W6, b6, out);
}